// round 1
// baseline (speedup 1.0000x reference)
#include <cuda_runtime.h>

// Problem constants
#define B_      4
#define N_      4096
#define DIM_    512
#define H_      8
#define DH_     64
#define M_      256
#define BH_     32          // B_*H_
#define ITERS_  6
#define KC_     33

// ------------------------- scratch (device globals) -------------------------
__device__ float g_xn  [B_ * N_ * DIM_];
__device__ float g_q   [BH_ * N_ * DH_];
__device__ float g_k   [BH_ * N_ * DH_];
__device__ float g_v   [BH_ * N_ * DH_];
__device__ float g_ql  [BH_ * M_ * DH_];
__device__ float g_kl  [BH_ * M_ * DH_];
__device__ float g_a1  [BH_ * N_ * M_];
__device__ float g_a3  [BH_ * M_ * N_];
__device__ float g_a2  [BH_ * M_ * M_];
__device__ float g_zA  [BH_ * M_ * M_];
__device__ float g_zB  [BH_ * M_ * M_];
__device__ float g_xz  [BH_ * M_ * M_];
__device__ float g_t1  [BH_ * M_ * M_];
__device__ float g_t2  [BH_ * M_ * M_];
__device__ float g_a3v [BH_ * M_ * DH_];
__device__ float g_zv  [BH_ * M_ * DH_];
__device__ float g_oat [BH_ * N_ * DH_];
__device__ float g_outc[B_ * N_ * DIM_];
__device__ unsigned g_maxc, g_maxr;

// ------------------------- reductions -------------------------
__device__ __forceinline__ float warpSum(float v) {
#pragma unroll
    for (int o = 16; o > 0; o >>= 1) v += __shfl_xor_sync(0xffffffffu, v, o);
    return v;
}
__device__ __forceinline__ float warpMax(float v) {
#pragma unroll
    for (int o = 16; o > 0; o >>= 1) v = fmaxf(v, __shfl_xor_sync(0xffffffffu, v, o));
    return v;
}
__device__ __forceinline__ float blockSum(float v, float* sh, int nw) {
    int l = threadIdx.x & 31, w = threadIdx.x >> 5;
    v = warpSum(v);
    if (l == 0) sh[w] = v;
    __syncthreads();
    if (w == 0) {
        float x = (l < nw) ? sh[l] : 0.f;
        x = warpSum(x);
        if (l == 0) sh[0] = x;
    }
    __syncthreads();
    float r = sh[0];
    __syncthreads();
    return r;
}
__device__ __forceinline__ float blockMax(float v, float* sh, int nw) {
    int l = threadIdx.x & 31, w = threadIdx.x >> 5;
    v = warpMax(v);
    if (l == 0) sh[w] = v;
    __syncthreads();
    if (w == 0) {
        float x = (l < nw) ? sh[l] : -3.4e38f;
        x = warpMax(x);
        if (l == 0) sh[0] = x;
    }
    __syncthreads();
    float r = sh[0];
    __syncthreads();
    return r;
}

// ------------------------- layernorm -------------------------
__global__ void ln_kernel(const float* __restrict__ x, const float* __restrict__ w,
                          const float* __restrict__ b, float* __restrict__ xn) {
    __shared__ float sh[8];
    long long row = blockIdx.x;
    const float4* p = (const float4*)(x + row * DIM_);
    float4 v = p[threadIdx.x];                       // 128 threads * 4
    float s  = v.x + v.y + v.z + v.w;
    float sq = v.x * v.x + v.y * v.y + v.z * v.z + v.w * v.w;
    s  = blockSum(s,  sh, 4);
    sq = blockSum(sq, sh, 4);
    float mean = s * (1.f / DIM_);
    float var  = sq * (1.f / DIM_) - mean * mean;
    float rstd = rsqrtf(var + 1e-5f);
    float4 wv = ((const float4*)w)[threadIdx.x];
    float4 bv = ((const float4*)b)[threadIdx.x];
    float4 o;
    o.x = (v.x - mean) * rstd * wv.x + bv.x;
    o.y = (v.y - mean) * rstd * wv.y + bv.y;
    o.z = (v.z - mean) * rstd * wv.z + bv.z;
    o.w = (v.w - mean) * rstd * wv.w + bv.w;
    ((float4*)(xn + row * DIM_))[threadIdx.x] = o;
}

// ------------------------- generic register-tiled SGEMM -------------------------
// C[M,N] = alpha*(A @ opB) + beta*A  (beta path only used for square pinv GEMMs)
// EPI 0: standard.  EPI 1: qkv scatter into q/k/v (O1..O3).  EPI 2: += x + b_out.
template<int EPI, bool TRANSB>
__global__ __launch_bounds__(256) void gemm_kernel(
    const float* __restrict__ A, const float* __restrict__ B, float* __restrict__ C,
    int K, int lda, int ldb, int ldc,
    long long sA, long long sB, long long sC,
    float alpha, float beta,
    const float* __restrict__ E1, const float* __restrict__ E2,
    float* __restrict__ O1, float* __restrict__ O2, float* __restrict__ O3)
{
    __shared__ float As[16][64];
    __shared__ float Bs[16][64];
    int bz = blockIdx.z;
    A += (long long)bz * sA;
    B += (long long)bz * sB;
    if (C) C += (long long)bz * sC;
    int i0 = blockIdx.y * 64, j0 = blockIdx.x * 64;
    int tid = threadIdx.x;
    int tx = tid & 15, ty = tid >> 4;
    int arow = tid >> 2, ac4 = (tid & 3) << 2;     // A / trans-B tile loader
    int brow = tid >> 4, bc4 = (tid & 15) << 2;    // NN B tile loader
    float acc[4][4] = {};

    for (int k0 = 0; k0 < K; k0 += 16) {
        float4 av = *(const float4*)&A[(long long)(i0 + arow) * lda + k0 + ac4];
        As[ac4 + 0][arow] = av.x; As[ac4 + 1][arow] = av.y;
        As[ac4 + 2][arow] = av.z; As[ac4 + 3][arow] = av.w;
        if (TRANSB) {
            float4 bv = *(const float4*)&B[(long long)(j0 + arow) * ldb + k0 + ac4];
            Bs[ac4 + 0][arow] = bv.x; Bs[ac4 + 1][arow] = bv.y;
            Bs[ac4 + 2][arow] = bv.z; Bs[ac4 + 3][arow] = bv.w;
        } else {
            float4 bv = *(const float4*)&B[(long long)(k0 + brow) * ldb + j0 + bc4];
            *(float4*)&Bs[brow][bc4] = bv;
        }
        __syncthreads();
#pragma unroll
        for (int k = 0; k < 16; k++) {
            float a[4], bb[4];
#pragma unroll
            for (int i = 0; i < 4; i++) a[i] = As[k][(ty << 2) + i];
#pragma unroll
            for (int j = 0; j < 4; j++) bb[j] = Bs[k][(tx << 2) + j];
#pragma unroll
            for (int i = 0; i < 4; i++)
#pragma unroll
                for (int j = 0; j < 4; j++) acc[i][j] = fmaf(a[i], bb[j], acc[i][j]);
        }
        __syncthreads();
    }

#pragma unroll
    for (int i = 0; i < 4; i++) {
        int r = i0 + (ty << 2) + i;
#pragma unroll
        for (int j = 0; j < 4; j++) {
            int c = j0 + (tx << 2) + j;
            if (EPI == 0) {
                float v = alpha * acc[i][j];
                if (beta != 0.f) v += beta * A[(long long)r * lda + c];
                C[(long long)r * ldc + c] = v;
            } else if (EPI == 1) {
                int sec = c >> 9, rem = c & 511;
                int h = rem >> 6, d = rem & 63;
                int bb_ = r >> 12, nn_ = r & 4095;
                long long di = (((long long)(bb_ * H_ + h)) * N_ + nn_) * DH_ + d;
                if (sec == 0)      O1[di] = acc[i][j] * 0.125f;   // q * DH^-0.5
                else if (sec == 1) O2[di] = acc[i][j];
                else               O3[di] = acc[i][j];
            } else { // EPI == 2: final projection + residual + bias
                long long di = (long long)r * DIM_ + c;
                C[di] = acc[i][j] + E1[di] + E2[c];
            }
        }
    }
}

// ------------------------- landmarks (mean over 16 tokens) -------------------------
__global__ void landmark_kernel(const float* __restrict__ q, const float* __restrict__ k,
                                float* __restrict__ ql, float* __restrict__ kl) {
    int idx = blockIdx.x * 256 + threadIdx.x;      // BH_*M_*DH_ = 524288
    int d = idx & 63;
    int m = (idx >> 6) & 255;
    int bh = idx >> 14;
    long long base = ((long long)bh * N_ + m * 16) * DH_ + d;
    float sq = 0.f, sk = 0.f;
#pragma unroll
    for (int j = 0; j < 16; j++) {
        sq += q[base + (long long)j * DH_];
        sk += k[base + (long long)j * DH_];
    }
    ql[idx] = sq * (1.f / 16.f);
    kl[idx] = sk * (1.f / 16.f);
}

// ------------------------- softmax over last dim -------------------------
template<int PER>
__global__ void softmax_kernel(float* __restrict__ p) {
    __shared__ float sh[8];
    float* r = p + (long long)blockIdx.x * (PER * 256);
    float vals[PER];
    float mx = -3.4e38f;
#pragma unroll
    for (int i = 0; i < PER; i++) {
        vals[i] = r[threadIdx.x + i * 256];
        mx = fmaxf(mx, vals[i]);
    }
    mx = blockMax(mx, sh, 8);
    float s = 0.f;
#pragma unroll
    for (int i = 0; i < PER; i++) {
        vals[i] = expf(vals[i] - mx);
        s += vals[i];
    }
    s = blockSum(s, sh, 8);
    float inv = 1.f / s;
#pragma unroll
    for (int i = 0; i < PER; i++) r[threadIdx.x + i * 256] = vals[i] * inv;
}

// ------------------------- pinv init helpers -------------------------
__global__ void init_max_kernel() {
    if (threadIdx.x == 0) { g_maxc = 0u; g_maxr = 0u; }
}
__global__ void rowsum_max_kernel(const float* __restrict__ a2) {
    __shared__ float sh[8];
    long long row = blockIdx.x;                     // BH_*M_ rows
    float v = fabsf(a2[row * M_ + threadIdx.x]);
    float s = blockSum(v, sh, 8);
    if (threadIdx.x == 0) atomicMax(&g_maxc, __float_as_uint(s));
}
__global__ void colsum_max_kernel(const float* __restrict__ a2) {
    __shared__ float sh[8];
    int bh = blockIdx.x >> 8, j = blockIdx.x & 255;
    float v = fabsf(a2[(long long)bh * M_ * M_ + (long long)threadIdx.x * M_ + j]);
    float s = blockSum(v, sh, 8);
    if (threadIdx.x == 0) atomicMax(&g_maxr, __float_as_uint(s));
}
__global__ void zinit_kernel(const float* __restrict__ a2, float* __restrict__ z) {
    int idx = blockIdx.x * 256 + threadIdx.x;       // BH_*M_*M_
    int j = idx & 255, i = (idx >> 8) & 255, bh = idx >> 16;
    float scale = 1.f / (__uint_as_float(g_maxc) * __uint_as_float(g_maxr));
    z[idx] = a2[(long long)bh * M_ * M_ + (long long)j * M_ + i] * scale;
}

// ------------------------- depthwise residual conv + merge heads -------------------------
__global__ void conv_merge_kernel(const float* __restrict__ v, const float* __restrict__ oat,
                                  const float* __restrict__ wconv, float* __restrict__ outc) {
    int idx = blockIdx.x * 256 + threadIdx.x;       // BH_*N_*DH_ = 8388608
    int d = idx & 63;
    int n = (idx >> 6) & 4095;
    int bh = idx >> 18;
    int h = bh & 7, b = bh >> 3;
    const float* vb = v + (long long)bh * N_ * DH_ + d;
    float r = 0.f;
#pragma unroll
    for (int kk = 0; kk < KC_; kk++) {
        int np = n + kk - (KC_ / 2);
        if (np >= 0 && np < N_) r += vb[(long long)np * DH_] * wconv[h * KC_ + kk];
    }
    outc[((long long)b * N_ + n) * DIM_ + h * DH_ + d] = oat[idx] + r;
}

// ------------------------- host launcher -------------------------
extern "C" void kernel_launch(void* const* d_in, const int* in_sizes, int n_in,
                              void* d_out, int out_size) {
    const float* x      = (const float*)d_in[0];
    const float* ln_w   = (const float*)d_in[1];
    const float* ln_b   = (const float*)d_in[2];
    const float* w_qkv  = (const float*)d_in[3];
    const float* w_out  = (const float*)d_in[4];
    const float* b_out  = (const float*)d_in[5];
    const float* w_conv = (const float*)d_in[6];
    float* out = (float*)d_out;

    float *p_xn, *p_q, *p_k, *p_v, *p_ql, *p_kl, *p_a1, *p_a3, *p_a2;
    float *p_zA, *p_zB, *p_xz, *p_t1, *p_t2, *p_a3v, *p_zv, *p_oat, *p_outc;
    cudaGetSymbolAddress((void**)&p_xn,  g_xn);
    cudaGetSymbolAddress((void**)&p_q,   g_q);
    cudaGetSymbolAddress((void**)&p_k,   g_k);
    cudaGetSymbolAddress((void**)&p_v,   g_v);
    cudaGetSymbolAddress((void**)&p_ql,  g_ql);
    cudaGetSymbolAddress((void**)&p_kl,  g_kl);
    cudaGetSymbolAddress((void**)&p_a1,  g_a1);
    cudaGetSymbolAddress((void**)&p_a3,  g_a3);
    cudaGetSymbolAddress((void**)&p_a2,  g_a2);
    cudaGetSymbolAddress((void**)&p_zA,  g_zA);
    cudaGetSymbolAddress((void**)&p_zB,  g_zB);
    cudaGetSymbolAddress((void**)&p_xz,  g_xz);
    cudaGetSymbolAddress((void**)&p_t1,  g_t1);
    cudaGetSymbolAddress((void**)&p_t2,  g_t2);
    cudaGetSymbolAddress((void**)&p_a3v, g_a3v);
    cudaGetSymbolAddress((void**)&p_zv,  g_zv);
    cudaGetSymbolAddress((void**)&p_oat, g_oat);
    cudaGetSymbolAddress((void**)&p_outc,g_outc);

    const long long sQKV = (long long)N_ * DH_;     // 262144
    const long long sL   = (long long)M_ * DH_;     // 16384
    const long long sA1  = (long long)N_ * M_;      // 1048576
    const long long sM2  = (long long)M_ * M_;      // 65536

    // 1. LayerNorm
    ln_kernel<<<B_ * N_, 128>>>(x, ln_w, ln_b, p_xn);

    // 2. QKV GEMM [16384,512] @ [512,1536] -> scatter into q/k/v [bh,n,dh]
    gemm_kernel<1, false><<<dim3(24, 256, 1), 256>>>(
        p_xn, w_qkv, nullptr, 512, 512, 1536, 0, 0, 0, 0, 1.f, 0.f,
        nullptr, nullptr, p_q, p_k, p_v);

    // 3. Landmarks (mean over 16 tokens)
    landmark_kernel<<<(BH_ * M_ * DH_) / 256, 256>>>(p_q, p_k, p_ql, p_kl);

    // 4. sim1 = q @ kl^T  [4096,256]
    gemm_kernel<0, true><<<dim3(4, 64, BH_), 256>>>(
        p_q, p_kl, p_a1, 64, 64, 64, 256, sQKV, sL, sA1, 1.f, 0.f,
        nullptr, nullptr, nullptr, nullptr, nullptr);
    // 5. sim2 = ql @ kl^T [256,256]
    gemm_kernel<0, true><<<dim3(4, 4, BH_), 256>>>(
        p_ql, p_kl, p_a2, 64, 64, 64, 256, sL, sL, sM2, 1.f, 0.f,
        nullptr, nullptr, nullptr, nullptr, nullptr);
    // 6. sim3 = ql @ k^T  [256,4096]
    gemm_kernel<0, true><<<dim3(64, 4, BH_), 256>>>(
        p_ql, p_k, p_a3, 64, 64, 64, 4096, sL, sQKV, sA1, 1.f, 0.f,
        nullptr, nullptr, nullptr, nullptr, nullptr);

    // 7. Softmaxes
    softmax_kernel<1><<<BH_ * N_, 256>>>(p_a1);
    softmax_kernel<1><<<BH_ * M_, 256>>>(p_a2);
    softmax_kernel<16><<<BH_ * M_, 256>>>(p_a3);

    // 8. pinv init: global maxes of abs row/col sums, z = a2^T / (maxc*maxr)
    init_max_kernel<<<1, 32>>>();
    rowsum_max_kernel<<<BH_ * M_, 256>>>(p_a2);
    colsum_max_kernel<<<BH_ * M_, 256>>>(p_a2);
    zinit_kernel<<<(BH_ * M_ * M_) / 256, 256>>>(p_a2, p_zA);

    // 9. Newton-Schulz iterations (batched 256^3 GEMMs, 32 matrices)
    float* cur = p_zA;
    float* nxt = p_zB;
    for (int it = 0; it < ITERS_; it++) {
        gemm_kernel<0, false><<<dim3(4, 4, BH_), 256>>>(
            p_a2, cur, p_xz, 256, 256, 256, 256, sM2, sM2, sM2, 1.f, 0.f,
            nullptr, nullptr, nullptr, nullptr, nullptr);
        gemm_kernel<0, false><<<dim3(4, 4, BH_), 256>>>(
            p_xz, p_xz, p_t1, 256, 256, 256, 256, sM2, sM2, sM2, -1.f, 7.f,
            nullptr, nullptr, nullptr, nullptr, nullptr);
        gemm_kernel<0, false><<<dim3(4, 4, BH_), 256>>>(
            p_xz, p_t1, p_t2, 256, 256, 256, 256, sM2, sM2, sM2, -1.f, 15.f,
            nullptr, nullptr, nullptr, nullptr, nullptr);
        gemm_kernel<0, false><<<dim3(4, 4, BH_), 256>>>(
            cur, p_t2, nxt, 256, 256, 256, 256, sM2, sM2, sM2, -0.25f, 3.25f,
            nullptr, nullptr, nullptr, nullptr, nullptr);
        float* tmp = cur; cur = nxt; nxt = tmp;
    }

    // 10. a3v = a3 @ v   [256,64], K=4096
    gemm_kernel<0, false><<<dim3(1, 4, BH_), 256>>>(
        p_a3, p_v, p_a3v, 4096, 4096, 64, 64, sA1, sQKV, sL, 1.f, 0.f,
        nullptr, nullptr, nullptr, nullptr, nullptr);
    // 11. zv = a2inv @ a3v  [256,64]
    gemm_kernel<0, false><<<dim3(1, 4, BH_), 256>>>(
        cur, p_a3v, p_zv, 256, 256, 64, 64, sM2, sL, sL, 1.f, 0.f,
        nullptr, nullptr, nullptr, nullptr, nullptr);
    // 12. oattn = a1 @ zv  [4096,64]
    gemm_kernel<0, false><<<dim3(1, 64, BH_), 256>>>(
        p_a1, p_zv, p_oat, 256, 256, 64, 64, sA1, sL, sQKV, 1.f, 0.f,
        nullptr, nullptr, nullptr, nullptr, nullptr);

    // 13. depthwise conv residual + head merge -> [b*n, 512]
    conv_merge_kernel<<<(BH_ * N_ * DH_) / 256, 256>>>(p_v, p_oat, w_conv, p_outc);

    // 14. final: out = x + outc @ w_out + b_out
    gemm_kernel<2, false><<<dim3(8, 256, 1), 256>>>(
        p_outc, w_out, out, 512, 512, 512, 512, 0, 0, 0, 1.f, 0.f,
        x, b_out, nullptr, nullptr, nullptr);
}

// round 2
// speedup vs baseline: 1.0184x; 1.0184x over previous
#include <cuda_runtime.h>

// Problem constants
#define B_      4
#define N_      4096
#define DIM_    512
#define H_      8
#define DH_     64
#define M_      256
#define BH_     32          // B_*H_
#define ITERS_  6
#define KC_     33
#define SPLITS_ 8

// ------------------------- scratch (device globals) -------------------------
__device__ float g_xn  [B_ * N_ * DIM_];
__device__ float g_q   [BH_ * N_ * DH_];
__device__ float g_k   [BH_ * N_ * DH_];
__device__ float g_v   [BH_ * N_ * DH_];
__device__ float g_ql  [BH_ * M_ * DH_];
__device__ float g_kl  [BH_ * M_ * DH_];
__device__ float g_a1  [BH_ * N_ * M_];
__device__ float g_a3  [BH_ * M_ * N_];
__device__ float g_a2  [BH_ * M_ * M_];
__device__ float g_zA  [BH_ * M_ * M_];
__device__ float g_zB  [BH_ * M_ * M_];
__device__ float g_xz  [BH_ * M_ * M_];
__device__ float g_t1  [BH_ * M_ * M_];
__device__ float g_t2  [BH_ * M_ * M_];
__device__ float g_part[BH_ * SPLITS_ * M_ * DH_];
__device__ float g_a3v [BH_ * M_ * DH_];
__device__ float g_zv  [BH_ * M_ * DH_];
__device__ float g_oat [BH_ * N_ * DH_];
__device__ float g_outc[B_ * N_ * DIM_];
__device__ unsigned g_maxc, g_maxr;

// ------------------------- reductions -------------------------
__device__ __forceinline__ float warpSum(float v) {
#pragma unroll
    for (int o = 16; o > 0; o >>= 1) v += __shfl_xor_sync(0xffffffffu, v, o);
    return v;
}
__device__ __forceinline__ float warpMax(float v) {
#pragma unroll
    for (int o = 16; o > 0; o >>= 1) v = fmaxf(v, __shfl_xor_sync(0xffffffffu, v, o));
    return v;
}
__device__ __forceinline__ float blockSum(float v, float* sh, int nw) {
    int l = threadIdx.x & 31, w = threadIdx.x >> 5;
    v = warpSum(v);
    if (l == 0) sh[w] = v;
    __syncthreads();
    if (w == 0) {
        float x = (l < nw) ? sh[l] : 0.f;
        x = warpSum(x);
        if (l == 0) sh[0] = x;
    }
    __syncthreads();
    float r = sh[0];
    __syncthreads();
    return r;
}
__device__ __forceinline__ float blockMax(float v, float* sh, int nw) {
    int l = threadIdx.x & 31, w = threadIdx.x >> 5;
    v = warpMax(v);
    if (l == 0) sh[w] = v;
    __syncthreads();
    if (w == 0) {
        float x = (l < nw) ? sh[l] : -3.4e38f;
        x = warpMax(x);
        if (l == 0) sh[0] = x;
    }
    __syncthreads();
    float r = sh[0];
    __syncthreads();
    return r;
}

// ------------------------- layernorm -------------------------
__global__ void ln_kernel(const float* __restrict__ x, const float* __restrict__ w,
                          const float* __restrict__ b, float* __restrict__ xn) {
    __shared__ float sh[8];
    long long row = blockIdx.x;
    const float4* p = (const float4*)(x + row * DIM_);
    float4 v = p[threadIdx.x];                       // 128 threads * 4
    float s  = v.x + v.y + v.z + v.w;
    float sq = v.x * v.x + v.y * v.y + v.z * v.z + v.w * v.w;
    s  = blockSum(s,  sh, 4);
    sq = blockSum(sq, sh, 4);
    float mean = s * (1.f / DIM_);
    float var  = sq * (1.f / DIM_) - mean * mean;
    float rstd = rsqrtf(var + 1e-5f);
    float4 wv = ((const float4*)w)[threadIdx.x];
    float4 bv = ((const float4*)b)[threadIdx.x];
    float4 o;
    o.x = (v.x - mean) * rstd * wv.x + bv.x;
    o.y = (v.y - mean) * rstd * wv.y + bv.y;
    o.z = (v.z - mean) * rstd * wv.z + bv.z;
    o.w = (v.w - mean) * rstd * wv.w + bv.w;
    ((float4*)(xn + row * DIM_))[threadIdx.x] = o;
}

// ------------------------- register-tiled SGEMM (vectorized, double-buffered) -----
// C = alpha*(A @ opB) + beta*A  (beta path used by the square pinv GEMMs)
// EPI 0: standard.  EPI 1: qkv scatter into q/k/v.  EPI 2: += x + b_out.
// splitS > 1: blockIdx.z = bh*splitS + s; each split covers Kper of K, writing
// its own partial C slab of size sC at index z.
// Requires: BM*BK == 1024, BK*BN == 1024, (BM/TM)*(BN/TN) == 256.
template<int BM, int BN, int BK, int TM, int TN, int EPI, bool TRANSB>
__global__ __launch_bounds__(256) void gemm_kernel(
    const float* __restrict__ A, const float* __restrict__ B, float* __restrict__ C,
    int Kper, int lda, int ldb, int ldc,
    long long sA, long long sB, long long sC, int splitS,
    float alpha, float beta,
    const float* __restrict__ E1, const float* __restrict__ E2,
    float* __restrict__ O1, float* __restrict__ O2, float* __restrict__ O3)
{
    __shared__ float As[2][BK][BM];
    __shared__ float Bs[2][BK][BN];

    int z = blockIdx.z;
    int sp = z % splitS;
    int bz = z / splitS;
    A += bz * sA + (long long)sp * Kper;
    B += bz * sB + (TRANSB ? (long long)sp * Kper : (long long)sp * Kper * ldb);
    if (C) C += (long long)z * sC;

    const int i0 = blockIdx.y * BM, j0 = blockIdx.x * BN;
    const int tid = threadIdx.x;
    const int tx = tid % (BN / TN), ty = tid / (BN / TN);

    // A-style loader (also used for transposed B): 1024 elems, float4 per thread
    const int AR = tid / (BK / 4);
    const int AC = (tid % (BK / 4)) * 4;
    // NN B loader
    const int BR = tid / (BN / 4);
    const int BC = (tid % (BN / 4)) * 4;

    const float* Aptr = &A[(long long)(i0 + AR) * lda + AC];
    const float* Bptr = TRANSB ? &B[(long long)(j0 + AR) * ldb + AC]
                               : &B[(long long)BR * ldb + j0 + BC];

    float acc[TM][TN] = {};
    const int nt = Kper / BK;

    // prologue: tile 0 into buffer 0
    {
        float4 av = *(const float4*)Aptr;
        As[0][AC + 0][AR] = av.x; As[0][AC + 1][AR] = av.y;
        As[0][AC + 2][AR] = av.z; As[0][AC + 3][AR] = av.w;
        float4 bv = *(const float4*)Bptr;
        if (TRANSB) {
            Bs[0][AC + 0][AR] = bv.x; Bs[0][AC + 1][AR] = bv.y;
            Bs[0][AC + 2][AR] = bv.z; Bs[0][AC + 3][AR] = bv.w;
        } else {
            *(float4*)&Bs[0][BR][BC] = bv;
        }
    }
    __syncthreads();

    for (int t = 0; t < nt; t++) {
        const int cur = t & 1, nxtb = cur ^ 1;
        float4 nav, nbv;
        if (t + 1 < nt) {
            nav = *(const float4*)(Aptr + (long long)(t + 1) * BK);
            nbv = TRANSB ? *(const float4*)(Bptr + (long long)(t + 1) * BK)
                         : *(const float4*)(Bptr + (long long)(t + 1) * BK * ldb);
        }
#pragma unroll
        for (int k = 0; k < BK; k++) {
            float a[TM], b[TN];
            const float4* ap = (const float4*)&As[cur][k][ty * TM];
            const float4* bp = (const float4*)&Bs[cur][k][tx * TN];
#pragma unroll
            for (int i = 0; i < TM / 4; i++) {
                float4 v = ap[i];
                a[i * 4 + 0] = v.x; a[i * 4 + 1] = v.y; a[i * 4 + 2] = v.z; a[i * 4 + 3] = v.w;
            }
#pragma unroll
            for (int j = 0; j < TN / 4; j++) {
                float4 v = bp[j];
                b[j * 4 + 0] = v.x; b[j * 4 + 1] = v.y; b[j * 4 + 2] = v.z; b[j * 4 + 3] = v.w;
            }
#pragma unroll
            for (int i = 0; i < TM; i++)
#pragma unroll
                for (int j = 0; j < TN; j++) acc[i][j] = fmaf(a[i], b[j], acc[i][j]);
        }
        if (t + 1 < nt) {
            As[nxtb][AC + 0][AR] = nav.x; As[nxtb][AC + 1][AR] = nav.y;
            As[nxtb][AC + 2][AR] = nav.z; As[nxtb][AC + 3][AR] = nav.w;
            if (TRANSB) {
                Bs[nxtb][AC + 0][AR] = nbv.x; Bs[nxtb][AC + 1][AR] = nbv.y;
                Bs[nxtb][AC + 2][AR] = nbv.z; Bs[nxtb][AC + 3][AR] = nbv.w;
            } else {
                *(float4*)&Bs[nxtb][BR][BC] = nbv;
            }
        }
        __syncthreads();
    }

#pragma unroll
    for (int i = 0; i < TM; i++) {
        int r = i0 + ty * TM + i;
#pragma unroll
        for (int j = 0; j < TN; j++) {
            int c = j0 + tx * TN + j;
            if (EPI == 0) {
                float v = alpha * acc[i][j];
                if (beta != 0.f) v += beta * A[(long long)r * lda + c];
                C[(long long)r * ldc + c] = v;
            } else if (EPI == 1) {
                int sec = c >> 9, rem = c & 511;
                int h = rem >> 6, d = rem & 63;
                int bb_ = r >> 12, nn_ = r & 4095;
                long long di = (((long long)(bb_ * H_ + h)) * N_ + nn_) * DH_ + d;
                if (sec == 0)      O1[di] = acc[i][j] * 0.125f;   // q * DH^-0.5
                else if (sec == 1) O2[di] = acc[i][j];
                else               O3[di] = acc[i][j];
            } else { // EPI == 2: final projection + residual + bias
                long long di = (long long)r * DIM_ + c;
                C[di] = acc[i][j] + E1[di] + E2[c];
            }
        }
    }
}

// ------------------------- split-K partial reduce -------------------------
__global__ void splitk_reduce_kernel(const float* __restrict__ part, float* __restrict__ outp) {
    int idx = blockIdx.x * 256 + threadIdx.x;       // BH_*M_*DH_
    int bh = idx >> 14, rem = idx & 16383;
    float s = 0.f;
#pragma unroll
    for (int sp = 0; sp < SPLITS_; sp++)
        s += part[((long long)(bh * SPLITS_ + sp) << 14) + rem];
    outp[idx] = s;
}

// ------------------------- landmarks (mean over 16 tokens) -------------------------
__global__ void landmark_kernel(const float* __restrict__ q, const float* __restrict__ k,
                                float* __restrict__ ql, float* __restrict__ kl) {
    int idx = blockIdx.x * 256 + threadIdx.x;      // BH_*M_*DH_ = 524288
    int d = idx & 63;
    int m = (idx >> 6) & 255;
    int bh = idx >> 14;
    long long base = ((long long)bh * N_ + m * 16) * DH_ + d;
    float sq = 0.f, sk = 0.f;
#pragma unroll
    for (int j = 0; j < 16; j++) {
        sq += q[base + (long long)j * DH_];
        sk += k[base + (long long)j * DH_];
    }
    ql[idx] = sq * (1.f / 16.f);
    kl[idx] = sk * (1.f / 16.f);
}

// ------------------------- softmax over last dim -------------------------
template<int PER>
__global__ void softmax_kernel(float* __restrict__ p) {
    __shared__ float sh[8];
    float* r = p + (long long)blockIdx.x * (PER * 256);
    float vals[PER];
    float mx = -3.4e38f;
#pragma unroll
    for (int i = 0; i < PER; i++) {
        vals[i] = r[threadIdx.x + i * 256];
        mx = fmaxf(mx, vals[i]);
    }
    mx = blockMax(mx, sh, 8);
    float s = 0.f;
#pragma unroll
    for (int i = 0; i < PER; i++) {
        vals[i] = expf(vals[i] - mx);
        s += vals[i];
    }
    s = blockSum(s, sh, 8);
    float inv = 1.f / s;
#pragma unroll
    for (int i = 0; i < PER; i++) r[threadIdx.x + i * 256] = vals[i] * inv;
}

// ------------------------- pinv init helpers -------------------------
__global__ void init_max_kernel() {
    if (threadIdx.x == 0) { g_maxc = 0u; g_maxr = 0u; }
}
__global__ void rowsum_max_kernel(const float* __restrict__ a2) {
    __shared__ float sh[8];
    long long row = blockIdx.x;                     // BH_*M_ rows
    float v = fabsf(a2[row * M_ + threadIdx.x]);
    float s = blockSum(v, sh, 8);
    if (threadIdx.x == 0) atomicMax(&g_maxc, __float_as_uint(s));
}
__global__ void colsum_max_kernel(const float* __restrict__ a2) {
    __shared__ float sh[8];
    int bh = blockIdx.x >> 8, j = blockIdx.x & 255;
    float v = fabsf(a2[(long long)bh * M_ * M_ + (long long)threadIdx.x * M_ + j]);
    float s = blockSum(v, sh, 8);
    if (threadIdx.x == 0) atomicMax(&g_maxr, __float_as_uint(s));
}
__global__ void zinit_kernel(const float* __restrict__ a2, float* __restrict__ z) {
    int idx = blockIdx.x * 256 + threadIdx.x;       // BH_*M_*M_
    int j = idx & 255, i = (idx >> 8) & 255, bh = idx >> 16;
    float scale = 1.f / (__uint_as_float(g_maxc) * __uint_as_float(g_maxr));
    z[idx] = a2[(long long)bh * M_ * M_ + (long long)j * M_ + i] * scale;
}

// ------------------------- depthwise residual conv + merge heads -------------------------
__global__ void conv_merge_kernel(const float* __restrict__ v, const float* __restrict__ oat,
                                  const float* __restrict__ wconv, float* __restrict__ outc) {
    int idx = blockIdx.x * 256 + threadIdx.x;       // BH_*N_*DH_ = 8388608
    int d = idx & 63;
    int n = (idx >> 6) & 4095;
    int bh = idx >> 18;
    int h = bh & 7, b = bh >> 3;
    const float* vb = v + (long long)bh * N_ * DH_ + d;
    float r = 0.f;
#pragma unroll
    for (int kk = 0; kk < KC_; kk++) {
        int np = n + kk - (KC_ / 2);
        if (np >= 0 && np < N_) r += vb[(long long)np * DH_] * wconv[h * KC_ + kk];
    }
    outc[((long long)b * N_ + n) * DIM_ + h * DH_ + d] = oat[idx] + r;
}

// ------------------------- host launcher -------------------------
extern "C" void kernel_launch(void* const* d_in, const int* in_sizes, int n_in,
                              void* d_out, int out_size) {
    const float* x      = (const float*)d_in[0];
    const float* ln_w   = (const float*)d_in[1];
    const float* ln_b   = (const float*)d_in[2];
    const float* w_qkv  = (const float*)d_in[3];
    const float* w_out  = (const float*)d_in[4];
    const float* b_out  = (const float*)d_in[5];
    const float* w_conv = (const float*)d_in[6];
    float* out = (float*)d_out;

    float *p_xn, *p_q, *p_k, *p_v, *p_ql, *p_kl, *p_a1, *p_a3, *p_a2;
    float *p_zA, *p_zB, *p_xz, *p_t1, *p_t2, *p_part, *p_a3v, *p_zv, *p_oat, *p_outc;
    cudaGetSymbolAddress((void**)&p_xn,  g_xn);
    cudaGetSymbolAddress((void**)&p_q,   g_q);
    cudaGetSymbolAddress((void**)&p_k,   g_k);
    cudaGetSymbolAddress((void**)&p_v,   g_v);
    cudaGetSymbolAddress((void**)&p_ql,  g_ql);
    cudaGetSymbolAddress((void**)&p_kl,  g_kl);
    cudaGetSymbolAddress((void**)&p_a1,  g_a1);
    cudaGetSymbolAddress((void**)&p_a3,  g_a3);
    cudaGetSymbolAddress((void**)&p_a2,  g_a2);
    cudaGetSymbolAddress((void**)&p_zA,  g_zA);
    cudaGetSymbolAddress((void**)&p_zB,  g_zB);
    cudaGetSymbolAddress((void**)&p_xz,  g_xz);
    cudaGetSymbolAddress((void**)&p_t1,  g_t1);
    cudaGetSymbolAddress((void**)&p_t2,  g_t2);
    cudaGetSymbolAddress((void**)&p_part,g_part);
    cudaGetSymbolAddress((void**)&p_a3v, g_a3v);
    cudaGetSymbolAddress((void**)&p_zv,  g_zv);
    cudaGetSymbolAddress((void**)&p_oat, g_oat);
    cudaGetSymbolAddress((void**)&p_outc,g_outc);

    const long long sQKV = (long long)N_ * DH_;     // 262144
    const long long sL   = (long long)M_ * DH_;     // 16384
    const long long sA1  = (long long)N_ * M_;      // 1048576
    const long long sM2  = (long long)M_ * M_;      // 65536

    // 1. LayerNorm
    ln_kernel<<<B_ * N_, 128>>>(x, ln_w, ln_b, p_xn);

    // 2. QKV GEMM [16384,512] @ [512,1536] -> scatter into q/k/v [bh,n,dh]
    gemm_kernel<128, 128, 8, 8, 8, 1, false><<<dim3(12, 128, 1), 256>>>(
        p_xn, w_qkv, nullptr, 512, 512, 1536, 0, 0, 0, 0, 1, 1.f, 0.f,
        nullptr, nullptr, p_q, p_k, p_v);

    // 3. Landmarks (mean over 16 tokens)
    landmark_kernel<<<(BH_ * M_ * DH_) / 256, 256>>>(p_q, p_k, p_ql, p_kl);

    // 4. sim1 = q @ kl^T  [4096,256]
    gemm_kernel<128, 128, 8, 8, 8, 0, true><<<dim3(2, 32, BH_), 256>>>(
        p_q, p_kl, p_a1, 64, 64, 64, 256, sQKV, sL, sA1, 1, 1.f, 0.f,
        nullptr, nullptr, nullptr, nullptr, nullptr);
    // 5. sim2 = ql @ kl^T [256,256]
    gemm_kernel<64, 64, 16, 4, 4, 0, true><<<dim3(4, 4, BH_), 256>>>(
        p_ql, p_kl, p_a2, 64, 64, 64, 256, sL, sL, sM2, 1, 1.f, 0.f,
        nullptr, nullptr, nullptr, nullptr, nullptr);
    // 6. sim3 = ql @ k^T  [256,4096]
    gemm_kernel<128, 128, 8, 8, 8, 0, true><<<dim3(32, 2, BH_), 256>>>(
        p_ql, p_k, p_a3, 64, 64, 64, 4096, sL, sQKV, sA1, 1, 1.f, 0.f,
        nullptr, nullptr, nullptr, nullptr, nullptr);

    // 7. Softmaxes
    softmax_kernel<1><<<BH_ * N_, 256>>>(p_a1);
    softmax_kernel<1><<<BH_ * M_, 256>>>(p_a2);
    softmax_kernel<16><<<BH_ * M_, 256>>>(p_a3);

    // 8. pinv init: global maxes of abs row/col sums, z = a2^T / (maxc*maxr)
    init_max_kernel<<<1, 32>>>();
    rowsum_max_kernel<<<BH_ * M_, 256>>>(p_a2);
    colsum_max_kernel<<<BH_ * M_, 256>>>(p_a2);
    zinit_kernel<<<(BH_ * M_ * M_) / 256, 256>>>(p_a2, p_zA);

    // 9. Newton-Schulz iterations (batched 256^3 GEMMs, 32 matrices)
    float* cur = p_zA;
    float* nxt = p_zB;
    for (int it = 0; it < ITERS_; it++) {
        gemm_kernel<64, 64, 16, 4, 4, 0, false><<<dim3(4, 4, BH_), 256>>>(
            p_a2, cur, p_xz, 256, 256, 256, 256, sM2, sM2, sM2, 1, 1.f, 0.f,
            nullptr, nullptr, nullptr, nullptr, nullptr);
        gemm_kernel<64, 64, 16, 4, 4, 0, false><<<dim3(4, 4, BH_), 256>>>(
            p_xz, p_xz, p_t1, 256, 256, 256, 256, sM2, sM2, sM2, 1, -1.f, 7.f,
            nullptr, nullptr, nullptr, nullptr, nullptr);
        gemm_kernel<64, 64, 16, 4, 4, 0, false><<<dim3(4, 4, BH_), 256>>>(
            p_xz, p_t1, p_t2, 256, 256, 256, 256, sM2, sM2, sM2, 1, -1.f, 15.f,
            nullptr, nullptr, nullptr, nullptr, nullptr);
        gemm_kernel<64, 64, 16, 4, 4, 0, false><<<dim3(4, 4, BH_), 256>>>(
            cur, p_t2, nxt, 256, 256, 256, 256, sM2, sM2, sM2, 1, -0.25f, 3.25f,
            nullptr, nullptr, nullptr, nullptr, nullptr);
        float* tmp = cur; cur = nxt; nxt = tmp;
    }

    // 10. a3v = a3 @ v   [256,64] per bh, K=4096 -> split-K by 8
    gemm_kernel<64, 64, 16, 4, 4, 0, false><<<dim3(1, 4, BH_ * SPLITS_), 256>>>(
        p_a3, p_v, p_part, 4096 / SPLITS_, 4096, 64, 64, sA1, sQKV, sL, SPLITS_,
        1.f, 0.f, nullptr, nullptr, nullptr, nullptr, nullptr);
    splitk_reduce_kernel<<<(BH_ * M_ * DH_) / 256, 256>>>(p_part, p_a3v);

    // 11. zv = a2inv @ a3v  [256,64]
    gemm_kernel<64, 64, 16, 4, 4, 0, false><<<dim3(1, 4, BH_), 256>>>(
        cur, p_a3v, p_zv, 256, 256, 64, 64, sM2, sL, sL, 1, 1.f, 0.f,
        nullptr, nullptr, nullptr, nullptr, nullptr);
    // 12. oattn = a1 @ zv  [4096,64]
    gemm_kernel<64, 64, 16, 4, 4, 0, false><<<dim3(1, 64, BH_), 256>>>(
        p_a1, p_zv, p_oat, 256, 256, 64, 64, sA1, sL, sQKV, 1, 1.f, 0.f,
        nullptr, nullptr, nullptr, nullptr, nullptr);

    // 13. depthwise conv residual + head merge -> [b*n, 512]
    conv_merge_kernel<<<(BH_ * N_ * DH_) / 256, 256>>>(p_v, p_oat, w_conv, p_outc);

    // 14. final: out = x + outc @ w_out + b_out
    gemm_kernel<128, 128, 8, 8, 8, 2, false><<<dim3(4, 128, 1), 256>>>(
        p_outc, w_out, out, 512, 512, 512, 512, 0, 0, 0, 1, 1.f, 0.f,
        x, b_out, nullptr, nullptr, nullptr);
}

// round 3
// speedup vs baseline: 2.4176x; 2.3739x over previous
#include <cuda_runtime.h>
#include <cstdint>

// Problem constants
#define B_      4
#define N_      4096
#define DIM_    512
#define H_      8
#define DH_     64
#define M_      256
#define BH_     32          // B_*H_
#define ITERS_  6
#define KC_     33
#define SPLITS_ 8

// ------------------------- scratch (device globals) -------------------------
__device__ float g_xn  [B_ * N_ * DIM_];
__device__ float g_q   [BH_ * N_ * DH_];
__device__ float g_k   [BH_ * N_ * DH_];
__device__ float g_v   [BH_ * N_ * DH_];
__device__ float g_ql  [BH_ * M_ * DH_];
__device__ float g_kl  [BH_ * M_ * DH_];
__device__ float g_a1  [BH_ * N_ * M_];
__device__ float g_a3  [BH_ * M_ * N_];
__device__ float g_a2  [BH_ * M_ * M_];
__device__ float g_zA  [BH_ * M_ * M_];
__device__ float g_zB  [BH_ * M_ * M_];
__device__ float g_xz  [BH_ * M_ * M_];
__device__ float g_t1  [BH_ * M_ * M_];
__device__ float g_t2  [BH_ * M_ * M_];
__device__ float g_part[BH_ * SPLITS_ * M_ * DH_];
__device__ float g_a3v [BH_ * M_ * DH_];
__device__ float g_zv  [BH_ * M_ * DH_];
__device__ float g_oat [BH_ * N_ * DH_];
__device__ float g_outc[B_ * N_ * DIM_];
__device__ unsigned g_maxc, g_maxr;

// ------------------------- reductions -------------------------
__device__ __forceinline__ float warpSum(float v) {
#pragma unroll
    for (int o = 16; o > 0; o >>= 1) v += __shfl_xor_sync(0xffffffffu, v, o);
    return v;
}
__device__ __forceinline__ float warpMax(float v) {
#pragma unroll
    for (int o = 16; o > 0; o >>= 1) v = fmaxf(v, __shfl_xor_sync(0xffffffffu, v, o));
    return v;
}
__device__ __forceinline__ float blockSum(float v, float* sh, int nw) {
    int l = threadIdx.x & 31, w = threadIdx.x >> 5;
    v = warpSum(v);
    if (l == 0) sh[w] = v;
    __syncthreads();
    if (w == 0) {
        float x = (l < nw) ? sh[l] : 0.f;
        x = warpSum(x);
        if (l == 0) sh[0] = x;
    }
    __syncthreads();
    float r = sh[0];
    __syncthreads();
    return r;
}
__device__ __forceinline__ float blockMax(float v, float* sh, int nw) {
    int l = threadIdx.x & 31, w = threadIdx.x >> 5;
    v = warpMax(v);
    if (l == 0) sh[w] = v;
    __syncthreads();
    if (w == 0) {
        float x = (l < nw) ? sh[l] : -3.4e38f;
        x = warpMax(x);
        if (l == 0) sh[0] = x;
    }
    __syncthreads();
    float r = sh[0];
    __syncthreads();
    return r;
}

// ------------------------- tf32 helpers -------------------------
__device__ __forceinline__ float f2tf(float x) {
    uint32_t r;
    asm("cvt.rna.tf32.f32 %0, %1;" : "=r"(r) : "f"(x));
    return __uint_as_float(r);
}
__device__ __forceinline__ float4 f2tf4(float4 v) {
    return make_float4(f2tf(v.x), f2tf(v.y), f2tf(v.z), f2tf(v.w));
}
__device__ __forceinline__ void mma8(float* d, const uint32_t* a, const uint32_t* b) {
    asm volatile(
        "mma.sync.aligned.m16n8k8.row.col.f32.tf32.tf32.f32 "
        "{%0,%1,%2,%3}, {%4,%5,%6,%7}, {%8,%9}, {%0,%1,%2,%3};\n"
        : "+f"(d[0]), "+f"(d[1]), "+f"(d[2]), "+f"(d[3])
        : "r"(a[0]), "r"(a[1]), "r"(a[2]), "r"(a[3]), "r"(b[0]), "r"(b[1]));
}

// ------------------------- layernorm -------------------------
__global__ void ln_kernel(const float* __restrict__ x, const float* __restrict__ w,
                          const float* __restrict__ b, float* __restrict__ xn) {
    __shared__ float sh[8];
    long long row = blockIdx.x;
    const float4* p = (const float4*)(x + row * DIM_);
    float4 v = p[threadIdx.x];                       // 128 threads * 4
    float s  = v.x + v.y + v.z + v.w;
    float sq = v.x * v.x + v.y * v.y + v.z * v.z + v.w * v.w;
    s  = blockSum(s,  sh, 4);
    sq = blockSum(sq, sh, 4);
    float mean = s * (1.f / DIM_);
    float var  = sq * (1.f / DIM_) - mean * mean;
    float rstd = rsqrtf(var + 1e-5f);
    float4 wv = ((const float4*)w)[threadIdx.x];
    float4 bv = ((const float4*)b)[threadIdx.x];
    float4 o;
    o.x = (v.x - mean) * rstd * wv.x + bv.x;
    o.y = (v.y - mean) * rstd * wv.y + bv.y;
    o.z = (v.z - mean) * rstd * wv.z + bv.z;
    o.w = (v.w - mean) * rstd * wv.w + bv.w;
    ((float4*)(xn + row * DIM_))[threadIdx.x] = o;
}

// ------------------------- tf32 tensor-core GEMM -------------------------
// C = alpha*(A @ opB) + beta*A   (beta path used by square pinv GEMMs)
// EPI 0: standard.  EPI 1: qkv scatter into q/k/v.  EPI 2: += x + b_out.
// splitS > 1: blockIdx.z = bh*splitS + sp; split covers Kper of K, writes its
// own partial C slab (size sC) at index z.
// 256 threads = 8 warps.  BK = 16.  Warp grid WRS x (8/WRS); warp tile
// (BM/WRS) x (BN*WRS/8); fragments m16n8k8 tf32.
template<int BM, int BN, int WRS, int EPI, bool TRANSB>
__global__ __launch_bounds__(256) void mma_gemm(
    const float* __restrict__ A, const float* __restrict__ B, float* __restrict__ C,
    int Kper, int lda, int ldb, int ldc,
    long long sA, long long sB, long long sC, int splitS,
    float alpha, float beta,
    const float* __restrict__ E1, const float* __restrict__ E2,
    float* __restrict__ O1, float* __restrict__ O2, float* __restrict__ O3)
{
    constexpr int BK  = 16;
    constexpr int WCS = 8 / WRS;
    constexpr int WM  = BM / WRS;
    constexpr int WN  = BN / WCS;
    constexpr int FM  = WM / 16;
    constexpr int FN  = WN / 8;
    constexpr int SKA = BK + 4;      // 20: conflict-free A frag loads
    constexpr int SNB = BN + 8;      // conflict-free B frag loads
    constexpr int AREP = BM / 64;
    constexpr int BREP = BN / 64;

    __shared__ float As[2][BM][SKA];   // [m][k]
    __shared__ float Bs[2][BK][SNB];   // [k][n]

    const int z  = blockIdx.z;
    const int sp = z % splitS;
    const int bz = z / splitS;
    A += bz * sA + (long long)sp * Kper;
    B += bz * sB + (TRANSB ? (long long)sp * Kper : (long long)sp * Kper * ldb);
    if (C) C += (long long)z * sC;

    const int i0 = blockIdx.y * BM, j0 = blockIdx.x * BN;
    const int tid  = threadIdx.x;
    const int lane = tid & 31, g = lane >> 2, tig = lane & 3;
    const int wid  = tid >> 5;
    const int wm   = (wid / WCS) * WM;
    const int wn   = (wid % WCS) * WN;

    // loaders
    const int arow = tid >> 2, ac4 = (tid & 3) << 2;       // A & trans-B: rows x k16
    const int bnn4 = BN / 4;
    const int bk0  = tid / bnn4, bn4 = (tid % bnn4) << 2;  // NN B: k x n
    const int bkstep = 1024 / BN;

    const float* Aptr = &A[(long long)(i0 + arow) * lda + ac4];
    const float* Bptr = TRANSB ? &B[(long long)(j0 + arow) * ldb + ac4]
                               : &B[(long long)bk0 * ldb + j0 + bn4];

    float acc[FM][FN][4] = {};
    const int nt = Kper / BK;

    float4 stA[AREP], stB[BREP];

    // ---- prologue: tile 0 ----
#pragma unroll
    for (int r = 0; r < AREP; r++) stA[r] = *(const float4*)(Aptr + (long long)r * 64 * lda);
#pragma unroll
    for (int r = 0; r < BREP; r++)
        stB[r] = TRANSB ? *(const float4*)(Bptr + (long long)r * 64 * ldb)
                        : *(const float4*)(Bptr + (long long)r * bkstep * ldb);
#pragma unroll
    for (int r = 0; r < AREP; r++)
        *(float4*)&As[0][arow + r * 64][ac4] = f2tf4(stA[r]);
#pragma unroll
    for (int r = 0; r < BREP; r++) {
        float4 bv = f2tf4(stB[r]);
        if (TRANSB) {
            Bs[0][ac4 + 0][arow + r * 64] = bv.x; Bs[0][ac4 + 1][arow + r * 64] = bv.y;
            Bs[0][ac4 + 2][arow + r * 64] = bv.z; Bs[0][ac4 + 3][arow + r * 64] = bv.w;
        } else {
            *(float4*)&Bs[0][bk0 + r * bkstep][bn4] = bv;
        }
    }
    __syncthreads();

    for (int t = 0; t < nt; t++) {
        const int cur = t & 1, nb = cur ^ 1;
        if (t + 1 < nt) {
            const long long ko = (long long)(t + 1) * BK;
#pragma unroll
            for (int r = 0; r < AREP; r++)
                stA[r] = *(const float4*)(Aptr + (long long)r * 64 * lda + ko);
#pragma unroll
            for (int r = 0; r < BREP; r++)
                stB[r] = TRANSB ? *(const float4*)(Bptr + (long long)r * 64 * ldb + ko)
                                : *(const float4*)(Bptr + ((long long)r * bkstep + ko) * ldb);
        }
#pragma unroll
        for (int ks = 0; ks < 2; ks++) {
            const int kb = ks * 8;
            uint32_t af[FM][4], bf[FN][2];
#pragma unroll
            for (int mi = 0; mi < FM; mi++) {
                const int row = wm + mi * 16 + g;
                af[mi][0] = __float_as_uint(As[cur][row    ][kb + tig]);
                af[mi][1] = __float_as_uint(As[cur][row + 8][kb + tig]);
                af[mi][2] = __float_as_uint(As[cur][row    ][kb + tig + 4]);
                af[mi][3] = __float_as_uint(As[cur][row + 8][kb + tig + 4]);
            }
#pragma unroll
            for (int ni = 0; ni < FN; ni++) {
                const int col = wn + ni * 8 + g;
                bf[ni][0] = __float_as_uint(Bs[cur][kb + tig    ][col]);
                bf[ni][1] = __float_as_uint(Bs[cur][kb + tig + 4][col]);
            }
#pragma unroll
            for (int mi = 0; mi < FM; mi++)
#pragma unroll
                for (int ni = 0; ni < FN; ni++) mma8(acc[mi][ni], af[mi], bf[ni]);
        }
        if (t + 1 < nt) {
#pragma unroll
            for (int r = 0; r < AREP; r++)
                *(float4*)&As[nb][arow + r * 64][ac4] = f2tf4(stA[r]);
#pragma unroll
            for (int r = 0; r < BREP; r++) {
                float4 bv = f2tf4(stB[r]);
                if (TRANSB) {
                    Bs[nb][ac4 + 0][arow + r * 64] = bv.x; Bs[nb][ac4 + 1][arow + r * 64] = bv.y;
                    Bs[nb][ac4 + 2][arow + r * 64] = bv.z; Bs[nb][ac4 + 3][arow + r * 64] = bv.w;
                } else {
                    *(float4*)&Bs[nb][bk0 + r * bkstep][bn4] = bv;
                }
            }
        }
        __syncthreads();
    }

    // ---- epilogue ----
#pragma unroll
    for (int mi = 0; mi < FM; mi++) {
        const int r0 = i0 + wm + mi * 16 + g;
        const int r1 = r0 + 8;
#pragma unroll
        for (int ni = 0; ni < FN; ni++) {
            const int c0 = j0 + wn + ni * 8 + 2 * tig;
            const float* d = acc[mi][ni];
            if (EPI == 0) {
                float2 v0 = make_float2(alpha * d[0], alpha * d[1]);
                float2 v1 = make_float2(alpha * d[2], alpha * d[3]);
                if (beta != 0.f) {
                    float2 e0 = *(const float2*)&A[(long long)r0 * lda + c0];
                    float2 e1 = *(const float2*)&A[(long long)r1 * lda + c0];
                    v0.x += beta * e0.x; v0.y += beta * e0.y;
                    v1.x += beta * e1.x; v1.y += beta * e1.y;
                }
                *(float2*)&C[(long long)r0 * ldc + c0] = v0;
                *(float2*)&C[(long long)r1 * ldc + c0] = v1;
            } else if (EPI == 1) {
                const int sec = c0 >> 9, rem = c0 & 511;
                const int h = rem >> 6, dd = rem & 63;
#pragma unroll
                for (int half = 0; half < 2; half++) {
                    const int r = half ? r1 : r0;
                    const int bb_ = r >> 12, nn_ = r & 4095;
                    const long long di = (((long long)(bb_ * H_ + h)) * N_ + nn_) * DH_ + dd;
                    float2 v = half ? make_float2(d[2], d[3]) : make_float2(d[0], d[1]);
                    if (sec == 0) { v.x *= 0.125f; v.y *= 0.125f; *(float2*)&O1[di] = v; }
                    else if (sec == 1) *(float2*)&O2[di] = v;
                    else               *(float2*)&O3[di] = v;
                }
            } else { // EPI == 2
                const long long d0i = (long long)r0 * DIM_ + c0;
                const long long d1i = (long long)r1 * DIM_ + c0;
                float2 e0 = *(const float2*)&E1[d0i];
                float2 e1 = *(const float2*)&E1[d1i];
                float2 b2 = *(const float2*)&E2[c0];
                *(float2*)&C[d0i] = make_float2(d[0] + e0.x + b2.x, d[1] + e0.y + b2.y);
                *(float2*)&C[d1i] = make_float2(d[2] + e1.x + b2.x, d[3] + e1.y + b2.y);
            }
        }
    }
}

// ------------------------- split-K partial reduce -------------------------
__global__ void splitk_reduce_kernel(const float* __restrict__ part, float* __restrict__ outp) {
    int idx = blockIdx.x * 256 + threadIdx.x;       // BH_*M_*DH_
    int bh = idx >> 14, rem = idx & 16383;
    float s = 0.f;
#pragma unroll
    for (int sp = 0; sp < SPLITS_; sp++)
        s += part[((long long)(bh * SPLITS_ + sp) << 14) + rem];
    outp[idx] = s;
}

// ------------------------- landmarks (mean over 16 tokens) -------------------------
__global__ void landmark_kernel(const float* __restrict__ q, const float* __restrict__ k,
                                float* __restrict__ ql, float* __restrict__ kl) {
    int idx = blockIdx.x * 256 + threadIdx.x;      // BH_*M_*DH_ = 524288
    int d = idx & 63;
    int m = (idx >> 6) & 255;
    int bh = idx >> 14;
    long long base = ((long long)bh * N_ + m * 16) * DH_ + d;
    float sq = 0.f, sk = 0.f;
#pragma unroll
    for (int j = 0; j < 16; j++) {
        sq += q[base + (long long)j * DH_];
        sk += k[base + (long long)j * DH_];
    }
    ql[idx] = sq * (1.f / 16.f);
    kl[idx] = sk * (1.f / 16.f);
}

// ------------------------- softmax over last dim -------------------------
template<int PER>
__global__ void softmax_kernel(float* __restrict__ p) {
    __shared__ float sh[8];
    float* r = p + (long long)blockIdx.x * (PER * 256);
    float vals[PER];
    float mx = -3.4e38f;
#pragma unroll
    for (int i = 0; i < PER; i++) {
        vals[i] = r[threadIdx.x + i * 256];
        mx = fmaxf(mx, vals[i]);
    }
    mx = blockMax(mx, sh, 8);
    float s = 0.f;
#pragma unroll
    for (int i = 0; i < PER; i++) {
        vals[i] = expf(vals[i] - mx);
        s += vals[i];
    }
    s = blockSum(s, sh, 8);
    float inv = 1.f / s;
#pragma unroll
    for (int i = 0; i < PER; i++) r[threadIdx.x + i * 256] = vals[i] * inv;
}

// ------------------------- pinv init helpers -------------------------
__global__ void init_max_kernel() {
    if (threadIdx.x == 0) { g_maxc = 0u; g_maxr = 0u; }
}
__global__ void rowsum_max_kernel(const float* __restrict__ a2) {
    __shared__ float sh[8];
    long long row = blockIdx.x;                     // BH_*M_ rows
    float v = fabsf(a2[row * M_ + threadIdx.x]);
    float s = blockSum(v, sh, 8);
    if (threadIdx.x == 0) atomicMax(&g_maxc, __float_as_uint(s));
}
__global__ void colsum_max_kernel(const float* __restrict__ a2) {
    __shared__ float sh[8];
    int bh = blockIdx.x >> 8, j = blockIdx.x & 255;
    float v = fabsf(a2[(long long)bh * M_ * M_ + (long long)threadIdx.x * M_ + j]);
    float s = blockSum(v, sh, 8);
    if (threadIdx.x == 0) atomicMax(&g_maxr, __float_as_uint(s));
}
__global__ void zinit_kernel(const float* __restrict__ a2, float* __restrict__ z) {
    int idx = blockIdx.x * 256 + threadIdx.x;       // BH_*M_*M_
    int j = idx & 255, i = (idx >> 8) & 255, bh = idx >> 16;
    float scale = 1.f / (__uint_as_float(g_maxc) * __uint_as_float(g_maxr));
    z[idx] = a2[(long long)bh * M_ * M_ + (long long)j * M_ + i] * scale;
}

// ------------------------- depthwise residual conv + merge heads -------------------------
__global__ void conv_merge_kernel(const float* __restrict__ v, const float* __restrict__ oat,
                                  const float* __restrict__ wconv, float* __restrict__ outc) {
    int idx = blockIdx.x * 256 + threadIdx.x;       // BH_*N_*DH_ = 8388608
    int d = idx & 63;
    int n = (idx >> 6) & 4095;
    int bh = idx >> 18;
    int h = bh & 7, b = bh >> 3;
    const float* vb = v + (long long)bh * N_ * DH_ + d;
    float r = 0.f;
#pragma unroll
    for (int kk = 0; kk < KC_; kk++) {
        int np = n + kk - (KC_ / 2);
        if (np >= 0 && np < N_) r += vb[(long long)np * DH_] * wconv[h * KC_ + kk];
    }
    outc[((long long)b * N_ + n) * DIM_ + h * DH_ + d] = oat[idx] + r;
}

// ------------------------- host launcher -------------------------
extern "C" void kernel_launch(void* const* d_in, const int* in_sizes, int n_in,
                              void* d_out, int out_size) {
    const float* x      = (const float*)d_in[0];
    const float* ln_w   = (const float*)d_in[1];
    const float* ln_b   = (const float*)d_in[2];
    const float* w_qkv  = (const float*)d_in[3];
    const float* w_out  = (const float*)d_in[4];
    const float* b_out  = (const float*)d_in[5];
    const float* w_conv = (const float*)d_in[6];
    float* out = (float*)d_out;

    float *p_xn, *p_q, *p_k, *p_v, *p_ql, *p_kl, *p_a1, *p_a3, *p_a2;
    float *p_zA, *p_zB, *p_xz, *p_t1, *p_t2, *p_part, *p_a3v, *p_zv, *p_oat, *p_outc;
    cudaGetSymbolAddress((void**)&p_xn,  g_xn);
    cudaGetSymbolAddress((void**)&p_q,   g_q);
    cudaGetSymbolAddress((void**)&p_k,   g_k);
    cudaGetSymbolAddress((void**)&p_v,   g_v);
    cudaGetSymbolAddress((void**)&p_ql,  g_ql);
    cudaGetSymbolAddress((void**)&p_kl,  g_kl);
    cudaGetSymbolAddress((void**)&p_a1,  g_a1);
    cudaGetSymbolAddress((void**)&p_a3,  g_a3);
    cudaGetSymbolAddress((void**)&p_a2,  g_a2);
    cudaGetSymbolAddress((void**)&p_zA,  g_zA);
    cudaGetSymbolAddress((void**)&p_zB,  g_zB);
    cudaGetSymbolAddress((void**)&p_xz,  g_xz);
    cudaGetSymbolAddress((void**)&p_t1,  g_t1);
    cudaGetSymbolAddress((void**)&p_t2,  g_t2);
    cudaGetSymbolAddress((void**)&p_part,g_part);
    cudaGetSymbolAddress((void**)&p_a3v, g_a3v);
    cudaGetSymbolAddress((void**)&p_zv,  g_zv);
    cudaGetSymbolAddress((void**)&p_oat, g_oat);
    cudaGetSymbolAddress((void**)&p_outc,g_outc);

    const long long sQKV = (long long)N_ * DH_;     // 262144
    const long long sL   = (long long)M_ * DH_;     // 16384
    const long long sA1  = (long long)N_ * M_;      // 1048576
    const long long sM2  = (long long)M_ * M_;      // 65536

    // 1. LayerNorm
    ln_kernel<<<B_ * N_, 128>>>(x, ln_w, ln_b, p_xn);

    // 2. QKV GEMM [16384,512] @ [512,1536] -> scatter into q/k/v [bh,n,dh]
    mma_gemm<128, 128, 2, 1, false><<<dim3(12, 128, 1), 256>>>(
        p_xn, w_qkv, nullptr, 512, 512, 1536, 0, 0, 0, 0, 1, 1.f, 0.f,
        nullptr, nullptr, p_q, p_k, p_v);

    // 3. Landmarks (mean over 16 tokens)
    landmark_kernel<<<(BH_ * M_ * DH_) / 256, 256>>>(p_q, p_k, p_ql, p_kl);

    // 4. sim1 = q @ kl^T  [4096,256]
    mma_gemm<128, 128, 2, 0, true><<<dim3(2, 32, BH_), 256>>>(
        p_q, p_kl, p_a1, 64, 64, 64, 256, sQKV, sL, sA1, 1, 1.f, 0.f,
        nullptr, nullptr, nullptr, nullptr, nullptr);
    // 5. sim2 = ql @ kl^T [256,256]
    mma_gemm<128, 128, 2, 0, true><<<dim3(2, 2, BH_), 256>>>(
        p_ql, p_kl, p_a2, 64, 64, 64, 256, sL, sL, sM2, 1, 1.f, 0.f,
        nullptr, nullptr, nullptr, nullptr, nullptr);
    // 6. sim3 = ql @ k^T  [256,4096]
    mma_gemm<128, 128, 2, 0, true><<<dim3(32, 2, BH_), 256>>>(
        p_ql, p_k, p_a3, 64, 64, 64, 4096, sL, sQKV, sA1, 1, 1.f, 0.f,
        nullptr, nullptr, nullptr, nullptr, nullptr);

    // 7. Softmaxes
    softmax_kernel<1><<<BH_ * N_, 256>>>(p_a1);
    softmax_kernel<1><<<BH_ * M_, 256>>>(p_a2);
    softmax_kernel<16><<<BH_ * M_, 256>>>(p_a3);

    // 8. pinv init
    init_max_kernel<<<1, 32>>>();
    rowsum_max_kernel<<<BH_ * M_, 256>>>(p_a2);
    colsum_max_kernel<<<BH_ * M_, 256>>>(p_a2);
    zinit_kernel<<<(BH_ * M_ * M_) / 256, 256>>>(p_a2, p_zA);

    // 9. Newton-Schulz iterations (batched 256^3 GEMMs, 32 matrices)
    float* cur = p_zA;
    float* nxt = p_zB;
    for (int it = 0; it < ITERS_; it++) {
        mma_gemm<128, 128, 2, 0, false><<<dim3(2, 2, BH_), 256>>>(
            p_a2, cur, p_xz, 256, 256, 256, 256, sM2, sM2, sM2, 1, 1.f, 0.f,
            nullptr, nullptr, nullptr, nullptr, nullptr);
        mma_gemm<128, 128, 2, 0, false><<<dim3(2, 2, BH_), 256>>>(
            p_xz, p_xz, p_t1, 256, 256, 256, 256, sM2, sM2, sM2, 1, -1.f, 7.f,
            nullptr, nullptr, nullptr, nullptr, nullptr);
        mma_gemm<128, 128, 2, 0, false><<<dim3(2, 2, BH_), 256>>>(
            p_xz, p_t1, p_t2, 256, 256, 256, 256, sM2, sM2, sM2, 1, -1.f, 15.f,
            nullptr, nullptr, nullptr, nullptr, nullptr);
        mma_gemm<128, 128, 2, 0, false><<<dim3(2, 2, BH_), 256>>>(
            cur, p_t2, nxt, 256, 256, 256, 256, sM2, sM2, sM2, 1, -0.25f, 3.25f,
            nullptr, nullptr, nullptr, nullptr, nullptr);
        float* tmp = cur; cur = nxt; nxt = tmp;
    }

    // 10. a3v = a3 @ v   [256,64] per bh, K=4096 -> split-K by 8
    mma_gemm<128, 64, 4, 0, false><<<dim3(1, 2, BH_ * SPLITS_), 256>>>(
        p_a3, p_v, p_part, 4096 / SPLITS_, 4096, 64, 64, sA1, sQKV, sL, SPLITS_,
        1.f, 0.f, nullptr, nullptr, nullptr, nullptr, nullptr);
    splitk_reduce_kernel<<<(BH_ * M_ * DH_) / 256, 256>>>(p_part, p_a3v);

    // 11. zv = a2inv @ a3v  [256,64]
    mma_gemm<128, 64, 4, 0, false><<<dim3(1, 2, BH_), 256>>>(
        cur, p_a3v, p_zv, 256, 256, 64, 64, sM2, sL, sL, 1, 1.f, 0.f,
        nullptr, nullptr, nullptr, nullptr, nullptr);
    // 12. oattn = a1 @ zv  [4096,64]
    mma_gemm<128, 64, 4, 0, false><<<dim3(1, 32, BH_), 256>>>(
        p_a1, p_zv, p_oat, 256, 256, 64, 64, sA1, sL, sQKV, 1, 1.f, 0.f,
        nullptr, nullptr, nullptr, nullptr, nullptr);

    // 13. depthwise conv residual + head merge -> [b*n, 512]
    conv_merge_kernel<<<(BH_ * N_ * DH_) / 256, 256>>>(p_v, p_oat, w_conv, p_outc);

    // 14. final: out = x + outc @ w_out + b_out
    mma_gemm<128, 128, 2, 2, false><<<dim3(4, 128, 1), 256>>>(
        p_outc, w_out, out, 512, 512, 512, 512, 0, 0, 0, 1, 1.f, 0.f,
        x, b_out, nullptr, nullptr, nullptr);
}

// round 5
// speedup vs baseline: 2.8513x; 1.1794x over previous
#include <cuda_runtime.h>
#include <cstdint>

// Problem constants
#define B_      4
#define N_      4096
#define DIM_    512
#define H_      8
#define DH_     64
#define M_      256
#define BH_     32          // B_*H_
#define ITERS_  6
#define KC_     33

// ------------------------- scratch (device globals) -------------------------
__device__ float g_xn  [B_ * N_ * DIM_];
__device__ float g_q   [BH_ * N_ * DH_];
__device__ float g_k   [BH_ * N_ * DH_];
__device__ float g_v   [BH_ * N_ * DH_];
__device__ float g_ql  [BH_ * M_ * DH_];
__device__ float g_kl  [BH_ * M_ * DH_];
__device__ float g_a2  [BH_ * M_ * M_];
__device__ float g_zA  [BH_ * M_ * M_];
__device__ float g_zB  [BH_ * M_ * M_];
__device__ float g_xz  [BH_ * M_ * M_];
__device__ float g_t1  [BH_ * M_ * M_];
__device__ float g_t2  [BH_ * M_ * M_];
__device__ float g_a3v [BH_ * M_ * DH_];
__device__ float g_zv  [BH_ * M_ * DH_];
__device__ float g_oat [BH_ * N_ * DH_];
__device__ float g_outc[B_ * N_ * DIM_];
__device__ unsigned g_maxc, g_maxr;

// ------------------------- reductions -------------------------
__device__ __forceinline__ float warpSum(float v) {
#pragma unroll
    for (int o = 16; o > 0; o >>= 1) v += __shfl_xor_sync(0xffffffffu, v, o);
    return v;
}
__device__ __forceinline__ float warpMax(float v) {
#pragma unroll
    for (int o = 16; o > 0; o >>= 1) v = fmaxf(v, __shfl_xor_sync(0xffffffffu, v, o));
    return v;
}
__device__ __forceinline__ float blockSum(float v, float* sh, int nw) {
    int l = threadIdx.x & 31, w = threadIdx.x >> 5;
    v = warpSum(v);
    if (l == 0) sh[w] = v;
    __syncthreads();
    if (w == 0) {
        float x = (l < nw) ? sh[l] : 0.f;
        x = warpSum(x);
        if (l == 0) sh[0] = x;
    }
    __syncthreads();
    float r = sh[0];
    __syncthreads();
    return r;
}
__device__ __forceinline__ float blockMax(float v, float* sh, int nw) {
    int l = threadIdx.x & 31, w = threadIdx.x >> 5;
    v = warpMax(v);
    if (l == 0) sh[w] = v;
    __syncthreads();
    if (w == 0) {
        float x = (l < nw) ? sh[l] : -3.4e38f;
        x = warpMax(x);
        if (l == 0) sh[0] = x;
    }
    __syncthreads();
    float r = sh[0];
    __syncthreads();
    return r;
}

// ------------------------- tf32 helpers -------------------------
__device__ __forceinline__ float f2tf(float x) {
    uint32_t r;
    asm("cvt.rna.tf32.f32 %0, %1;" : "=r"(r) : "f"(x));
    return __uint_as_float(r);
}
__device__ __forceinline__ float4 f2tf4(float4 v) {
    return make_float4(f2tf(v.x), f2tf(v.y), f2tf(v.z), f2tf(v.w));
}
__device__ __forceinline__ void mma8(float* d, const uint32_t* a, const uint32_t* b) {
    asm volatile(
        "mma.sync.aligned.m16n8k8.row.col.f32.tf32.tf32.f32 "
        "{%0,%1,%2,%3}, {%4,%5,%6,%7}, {%8,%9}, {%0,%1,%2,%3};\n"
        : "+f"(d[0]), "+f"(d[1]), "+f"(d[2]), "+f"(d[3])
        : "r"(a[0]), "r"(a[1]), "r"(a[2]), "r"(a[3]), "r"(b[0]), "r"(b[1]));
}

// ------------------------- layernorm -------------------------
__global__ void ln_kernel(const float* __restrict__ x, const float* __restrict__ w,
                          const float* __restrict__ b, float* __restrict__ xn) {
    __shared__ float sh[8];
    long long row = blockIdx.x;
    const float4* p = (const float4*)(x + row * DIM_);
    float4 v = p[threadIdx.x];                       // 128 threads * 4
    float s  = v.x + v.y + v.z + v.w;
    float sq = v.x * v.x + v.y * v.y + v.z * v.z + v.w * v.w;
    s  = blockSum(s,  sh, 4);
    sq = blockSum(sq, sh, 4);
    float mean = s * (1.f / DIM_);
    float var  = sq * (1.f / DIM_) - mean * mean;
    float rstd = rsqrtf(var + 1e-5f);
    float4 wv = ((const float4*)w)[threadIdx.x];
    float4 bv = ((const float4*)b)[threadIdx.x];
    float4 o;
    o.x = (v.x - mean) * rstd * wv.x + bv.x;
    o.y = (v.y - mean) * rstd * wv.y + bv.y;
    o.z = (v.z - mean) * rstd * wv.z + bv.z;
    o.w = (v.w - mean) * rstd * wv.w + bv.w;
    ((float4*)(xn + row * DIM_))[threadIdx.x] = o;
}

// ------------------------- tf32 tensor-core GEMM -------------------------
// C = alpha*(A @ opB) + beta*A   (beta path used by square pinv GEMMs)
// EPI 0: standard.  EPI 1: qkv scatter into q/k/v.  EPI 2: += x + b_out.
template<int BM, int BN, int WRS, int EPI, bool TRANSB>
__global__ __launch_bounds__(256) void mma_gemm(
    const float* __restrict__ A, const float* __restrict__ B, float* __restrict__ C,
    int Kper, int lda, int ldb, int ldc,
    long long sA, long long sB, long long sC,
    float alpha, float beta,
    const float* __restrict__ E1, const float* __restrict__ E2,
    float* __restrict__ O1, float* __restrict__ O2, float* __restrict__ O3)
{
    constexpr int BK  = 16;
    constexpr int WCS = 8 / WRS;
    constexpr int WM  = BM / WRS;
    constexpr int WN  = BN / WCS;
    constexpr int FM  = WM / 16;
    constexpr int FN  = WN / 8;
    constexpr int SKA = BK + 4;
    constexpr int SNB = BN + 8;
    constexpr int AREP = BM / 64;
    constexpr int BREP = BN / 64;

    __shared__ float As[2][BM][SKA];   // [m][k]
    __shared__ float Bs[2][BK][SNB];   // [k][n]

    const int bz = blockIdx.z;
    A += bz * sA;
    B += bz * sB;
    if (C) C += bz * sC;

    const int i0 = blockIdx.y * BM, j0 = blockIdx.x * BN;
    const int tid  = threadIdx.x;
    const int lane = tid & 31, g = lane >> 2, tig = lane & 3;
    const int wid  = tid >> 5;
    const int wm   = (wid / WCS) * WM;
    const int wn   = (wid % WCS) * WN;

    const int arow = tid >> 2, ac4 = (tid & 3) << 2;
    const int bnn4 = BN / 4;
    const int bk0  = tid / bnn4, bn4 = (tid % bnn4) << 2;
    const int bkstep = 1024 / BN;

    const float* Aptr = &A[(long long)(i0 + arow) * lda + ac4];
    const float* Bptr = TRANSB ? &B[(long long)(j0 + arow) * ldb + ac4]
                               : &B[(long long)bk0 * ldb + j0 + bn4];

    float acc[FM][FN][4] = {};
    const int nt = Kper / BK;

    float4 stA[AREP], stB[BREP];

#pragma unroll
    for (int r = 0; r < AREP; r++) stA[r] = *(const float4*)(Aptr + (long long)r * 64 * lda);
#pragma unroll
    for (int r = 0; r < BREP; r++)
        stB[r] = TRANSB ? *(const float4*)(Bptr + (long long)r * 64 * ldb)
                        : *(const float4*)(Bptr + (long long)r * bkstep * ldb);
#pragma unroll
    for (int r = 0; r < AREP; r++)
        *(float4*)&As[0][arow + r * 64][ac4] = f2tf4(stA[r]);
#pragma unroll
    for (int r = 0; r < BREP; r++) {
        float4 bv = f2tf4(stB[r]);
        if (TRANSB) {
            Bs[0][ac4 + 0][arow + r * 64] = bv.x; Bs[0][ac4 + 1][arow + r * 64] = bv.y;
            Bs[0][ac4 + 2][arow + r * 64] = bv.z; Bs[0][ac4 + 3][arow + r * 64] = bv.w;
        } else {
            *(float4*)&Bs[0][bk0 + r * bkstep][bn4] = bv;
        }
    }
    __syncthreads();

    for (int t = 0; t < nt; t++) {
        const int cur = t & 1, nb = cur ^ 1;
        if (t + 1 < nt) {
            const long long ko = (long long)(t + 1) * BK;
#pragma unroll
            for (int r = 0; r < AREP; r++)
                stA[r] = *(const float4*)(Aptr + (long long)r * 64 * lda + ko);
#pragma unroll
            for (int r = 0; r < BREP; r++)
                stB[r] = TRANSB ? *(const float4*)(Bptr + (long long)r * 64 * ldb + ko)
                                : *(const float4*)(Bptr + ((long long)r * bkstep + ko) * ldb);
        }
#pragma unroll
        for (int ks = 0; ks < 2; ks++) {
            const int kb = ks * 8;
            uint32_t af[FM][4], bf[FN][2];
#pragma unroll
            for (int mi = 0; mi < FM; mi++) {
                const int row = wm + mi * 16 + g;
                af[mi][0] = __float_as_uint(As[cur][row    ][kb + tig]);
                af[mi][1] = __float_as_uint(As[cur][row + 8][kb + tig]);
                af[mi][2] = __float_as_uint(As[cur][row    ][kb + tig + 4]);
                af[mi][3] = __float_as_uint(As[cur][row + 8][kb + tig + 4]);
            }
#pragma unroll
            for (int ni = 0; ni < FN; ni++) {
                const int col = wn + ni * 8 + g;
                bf[ni][0] = __float_as_uint(Bs[cur][kb + tig    ][col]);
                bf[ni][1] = __float_as_uint(Bs[cur][kb + tig + 4][col]);
            }
#pragma unroll
            for (int mi = 0; mi < FM; mi++)
#pragma unroll
                for (int ni = 0; ni < FN; ni++) mma8(acc[mi][ni], af[mi], bf[ni]);
        }
        if (t + 1 < nt) {
#pragma unroll
            for (int r = 0; r < AREP; r++)
                *(float4*)&As[nb][arow + r * 64][ac4] = f2tf4(stA[r]);
#pragma unroll
            for (int r = 0; r < BREP; r++) {
                float4 bv = f2tf4(stB[r]);
                if (TRANSB) {
                    Bs[nb][ac4 + 0][arow + r * 64] = bv.x; Bs[nb][ac4 + 1][arow + r * 64] = bv.y;
                    Bs[nb][ac4 + 2][arow + r * 64] = bv.z; Bs[nb][ac4 + 3][arow + r * 64] = bv.w;
                } else {
                    *(float4*)&Bs[nb][bk0 + r * bkstep][bn4] = bv;
                }
            }
        }
        __syncthreads();
    }

#pragma unroll
    for (int mi = 0; mi < FM; mi++) {
        const int r0 = i0 + wm + mi * 16 + g;
        const int r1 = r0 + 8;
#pragma unroll
        for (int ni = 0; ni < FN; ni++) {
            const int c0 = j0 + wn + ni * 8 + 2 * tig;
            const float* d = acc[mi][ni];
            if (EPI == 0) {
                float2 v0 = make_float2(alpha * d[0], alpha * d[1]);
                float2 v1 = make_float2(alpha * d[2], alpha * d[3]);
                if (beta != 0.f) {
                    float2 e0 = *(const float2*)&A[(long long)r0 * lda + c0];
                    float2 e1 = *(const float2*)&A[(long long)r1 * lda + c0];
                    v0.x += beta * e0.x; v0.y += beta * e0.y;
                    v1.x += beta * e1.x; v1.y += beta * e1.y;
                }
                *(float2*)&C[(long long)r0 * ldc + c0] = v0;
                *(float2*)&C[(long long)r1 * ldc + c0] = v1;
            } else if (EPI == 1) {
                const int sec = c0 >> 9, rem = c0 & 511;
                const int h = rem >> 6, dd = rem & 63;
#pragma unroll
                for (int half = 0; half < 2; half++) {
                    const int r = half ? r1 : r0;
                    const int bb_ = r >> 12, nn_ = r & 4095;
                    const long long di = (((long long)(bb_ * H_ + h)) * N_ + nn_) * DH_ + dd;
                    float2 v = half ? make_float2(d[2], d[3]) : make_float2(d[0], d[1]);
                    if (sec == 0) { v.x *= 0.125f; v.y *= 0.125f; *(float2*)&O1[di] = v; }
                    else if (sec == 1) *(float2*)&O2[di] = v;
                    else               *(float2*)&O3[di] = v;
                }
            } else { // EPI == 2
                const long long d0i = (long long)r0 * DIM_ + c0;
                const long long d1i = (long long)r1 * DIM_ + c0;
                float2 e0 = *(const float2*)&E1[d0i];
                float2 e1 = *(const float2*)&E1[d1i];
                float2 b2 = *(const float2*)&E2[c0];
                *(float2*)&C[d0i] = make_float2(d[0] + e0.x + b2.x, d[1] + e0.y + b2.y);
                *(float2*)&C[d1i] = make_float2(d[2] + e1.x + b2.x, d[3] + e1.y + b2.y);
            }
        }
    }
}

// ------------------------- flash attention: O = softmax(Q@K^T) @ V -------------------
// Q: [bh, R, 64] (R = gridDim.x*64), K,V: [bh, C, 64], O: [bh, R, 64].
// 128 threads = 4 warps; each warp owns 16 rows; BC = 128 per chunk.
// Dynamic smem: Qs[64][68] | KP union(Ks[128][68], Ps[64][140]) | Vs[128][68].
#define FL_QS   0
#define FL_KP   (64 * 68)
#define FL_VS   (64 * 68 + 8960)
#define FL_SMEM ((64 * 68 + 8960 + 128 * 68) * 4)

__global__ __launch_bounds__(128) void flash_kernel(
    const float* __restrict__ Q, const float* __restrict__ K,
    const float* __restrict__ V, float* __restrict__ O, int C)
{
    extern __shared__ float sm[];
    float* Qs = sm + FL_QS;
    float* KP = sm + FL_KP;
    float* Vs = sm + FL_VS;

    const int bh = blockIdx.y;
    const long long qoff = ((long long)bh * gridDim.x + blockIdx.x) * 64 * 64;
    Q += qoff;  O += qoff;
    K += (long long)bh * C * 64;
    V += (long long)bh * C * 64;

    const int tid = threadIdx.x;
    const int lane = tid & 31, g = lane >> 2, tig = lane & 3;
    const int w = tid >> 5;
    const int r0l = w * 16 + g, r1l = r0l + 8;

    // load Q block (64x64)
#pragma unroll
    for (int i = 0; i < 8; i++) {
        int idx = tid + i * 128;
        int row = idx >> 4, c4 = (idx & 15) << 2;
        *(float4*)&Qs[row * 68 + c4] = f2tf4(*(const float4*)&Q[row * 64 + c4]);
    }

    float o[8][4] = {};
    float m0 = -1e30f, m1 = -1e30f, l0 = 0.f, l1 = 0.f;

    for (int c0 = 0; c0 < C; c0 += 128) {
        __syncthreads();
        // load K,V chunk (128x64 each)
#pragma unroll
        for (int i = 0; i < 16; i++) {
            int idx = tid + i * 128;
            int row = idx >> 4, c4 = (idx & 15) << 2;
            *(float4*)&KP[row * 68 + c4] = f2tf4(*(const float4*)&K[(long long)(c0 + row) * 64 + c4]);
            *(float4*)&Vs[row * 68 + c4] = f2tf4(*(const float4*)&V[(long long)(c0 + row) * 64 + c4]);
        }
        __syncthreads();

        // S = Q @ K^T  (16 rows x 128 cols per warp)
        float s[16][4] = {};
#pragma unroll
        for (int kb = 0; kb < 64; kb += 8) {
            uint32_t af[4];
            af[0] = __float_as_uint(Qs[r0l * 68 + kb + tig]);
            af[1] = __float_as_uint(Qs[r1l * 68 + kb + tig]);
            af[2] = __float_as_uint(Qs[r0l * 68 + kb + tig + 4]);
            af[3] = __float_as_uint(Qs[r1l * 68 + kb + tig + 4]);
#pragma unroll
            for (int ni = 0; ni < 16; ni++) {
                uint32_t bf[2];
                bf[0] = __float_as_uint(KP[(ni * 8 + g) * 68 + kb + tig]);
                bf[1] = __float_as_uint(KP[(ni * 8 + g) * 68 + kb + tig + 4]);
                mma8(s[ni], af, bf);
            }
        }

        // online softmax
        float cm0 = -1e30f, cm1 = -1e30f;
#pragma unroll
        for (int ni = 0; ni < 16; ni++) {
            cm0 = fmaxf(cm0, fmaxf(s[ni][0], s[ni][1]));
            cm1 = fmaxf(cm1, fmaxf(s[ni][2], s[ni][3]));
        }
        cm0 = fmaxf(cm0, __shfl_xor_sync(0xffffffffu, cm0, 1));
        cm0 = fmaxf(cm0, __shfl_xor_sync(0xffffffffu, cm0, 2));
        cm1 = fmaxf(cm1, __shfl_xor_sync(0xffffffffu, cm1, 1));
        cm1 = fmaxf(cm1, __shfl_xor_sync(0xffffffffu, cm1, 2));
        float M0 = fmaxf(m0, cm0), M1 = fmaxf(m1, cm1);
        float corr0 = __expf(m0 - M0), corr1 = __expf(m1 - M1);
        float sum0 = 0.f, sum1 = 0.f;
#pragma unroll
        for (int ni = 0; ni < 16; ni++) {
            s[ni][0] = __expf(s[ni][0] - M0);
            s[ni][1] = __expf(s[ni][1] - M0);
            s[ni][2] = __expf(s[ni][2] - M1);
            s[ni][3] = __expf(s[ni][3] - M1);
            sum0 += s[ni][0] + s[ni][1];
            sum1 += s[ni][2] + s[ni][3];
        }
        sum0 += __shfl_xor_sync(0xffffffffu, sum0, 1);
        sum0 += __shfl_xor_sync(0xffffffffu, sum0, 2);
        sum1 += __shfl_xor_sync(0xffffffffu, sum1, 1);
        sum1 += __shfl_xor_sync(0xffffffffu, sum1, 2);
        l0 = l0 * corr0 + sum0;
        l1 = l1 * corr1 + sum1;
        m0 = M0; m1 = M1;
#pragma unroll
        for (int ni = 0; ni < 8; ni++) {
            o[ni][0] *= corr0; o[ni][1] *= corr0;
            o[ni][2] *= corr1; o[ni][3] *= corr1;
        }

        __syncthreads();      // all warps done reading K tile (Ps aliases it)
        // write P (tf32) to Ps[64][140]
#pragma unroll
        for (int ni = 0; ni < 16; ni++) {
            int col = ni * 8 + 2 * tig;
            *(float2*)&KP[r0l * 140 + col] = make_float2(f2tf(s[ni][0]), f2tf(s[ni][1]));
            *(float2*)&KP[r1l * 140 + col] = make_float2(f2tf(s[ni][2]), f2tf(s[ni][3]));
        }
        __syncthreads();

        // O += P @ V   (K = 128)
#pragma unroll
        for (int kb = 0; kb < 128; kb += 8) {
            uint32_t af[4];
            af[0] = __float_as_uint(KP[r0l * 140 + kb + tig]);
            af[1] = __float_as_uint(KP[r1l * 140 + kb + tig]);
            af[2] = __float_as_uint(KP[r0l * 140 + kb + tig + 4]);
            af[3] = __float_as_uint(KP[r1l * 140 + kb + tig + 4]);
#pragma unroll
            for (int ni = 0; ni < 8; ni++) {
                uint32_t bf[2];
                bf[0] = __float_as_uint(Vs[(kb + tig) * 68 + ni * 8 + g]);
                bf[1] = __float_as_uint(Vs[(kb + tig + 4) * 68 + ni * 8 + g]);
                mma8(o[ni], af, bf);
            }
        }
    }

    const float inv0 = 1.f / l0, inv1 = 1.f / l1;
#pragma unroll
    for (int ni = 0; ni < 8; ni++) {
        int col = ni * 8 + 2 * tig;
        *(float2*)&O[r0l * 64 + col] = make_float2(o[ni][0] * inv0, o[ni][1] * inv0);
        *(float2*)&O[r1l * 64 + col] = make_float2(o[ni][2] * inv1, o[ni][3] * inv1);
    }
}

// ------------------------- landmarks (mean over 16 tokens) -------------------------
__global__ void landmark_kernel(const float* __restrict__ q, const float* __restrict__ k,
                                float* __restrict__ ql, float* __restrict__ kl) {
    int idx = blockIdx.x * 256 + threadIdx.x;      // BH_*M_*DH_ = 524288
    int d = idx & 63;
    int m = (idx >> 6) & 255;
    int bh = idx >> 14;
    long long base = ((long long)bh * N_ + m * 16) * DH_ + d;
    float sq = 0.f, sk = 0.f;
#pragma unroll
    for (int j = 0; j < 16; j++) {
        sq += q[base + (long long)j * DH_];
        sk += k[base + (long long)j * DH_];
    }
    ql[idx] = sq * (1.f / 16.f);
    kl[idx] = sk * (1.f / 16.f);
}

// ------------------------- softmax over last dim (a2 only) -------------------------
__global__ void softmax_kernel(float* __restrict__ p) {
    __shared__ float sh[8];
    float* r = p + (long long)blockIdx.x * 256;
    float v = r[threadIdx.x];
    float mx = blockMax(v, sh, 8);
    float e = expf(v - mx);
    float s = blockSum(e, sh, 8);
    r[threadIdx.x] = e / s;
}

// ------------------------- pinv init helpers -------------------------
__global__ void init_max_kernel() {
    if (threadIdx.x == 0) { g_maxc = 0u; g_maxr = 0u; }
}
__global__ void rowsum_max_kernel(const float* __restrict__ a2) {
    __shared__ float sh[8];
    long long row = blockIdx.x;                     // BH_*M_ rows
    float v = fabsf(a2[row * M_ + threadIdx.x]);
    float s = blockSum(v, sh, 8);
    if (threadIdx.x == 0) atomicMax(&g_maxc, __float_as_uint(s));
}
__global__ void colsum_max_kernel(const float* __restrict__ a2) {
    __shared__ float sh[8];
    int bh = blockIdx.x >> 8, j = blockIdx.x & 255;
    float v = fabsf(a2[(long long)bh * M_ * M_ + (long long)threadIdx.x * M_ + j]);
    float s = blockSum(v, sh, 8);
    if (threadIdx.x == 0) atomicMax(&g_maxr, __float_as_uint(s));
}
__global__ void zinit_kernel(const float* __restrict__ a2, float* __restrict__ z) {
    int idx = blockIdx.x * 256 + threadIdx.x;       // BH_*M_*M_
    int j = idx & 255, i = (idx >> 8) & 255, bh = idx >> 16;
    float scale = 1.f / (__uint_as_float(g_maxc) * __uint_as_float(g_maxr));
    z[idx] = a2[(long long)bh * M_ * M_ + (long long)j * M_ + i] * scale;
}

// ------------------------- tiled depthwise conv + merge heads -------------------------
#define VSTR 68
__global__ __launch_bounds__(256) void conv_merge_kernel(
    const float* __restrict__ v, const float* __restrict__ oat,
    const float* __restrict__ wconv, float* __restrict__ outc)
{
    __shared__ float vt[160 * VSTR];
    __shared__ float wc[KC_];
    const int bh = blockIdx.y, h = bh & 7, b = bh >> 3;
    const int n0 = blockIdx.x * 128;
    const int tid = threadIdx.x;
    if (tid < KC_) wc[tid] = wconv[h * KC_ + tid];
    const float* vb = v + (long long)bh * N_ * DH_;
#pragma unroll
    for (int i = 0; i < 10; i++) {
        int idx = tid + i * 256;                    // 2560 float4 slots = 160 rows x 16
        int row = idx >> 4, c4 = (idx & 15) << 2;
        int gn = n0 - 16 + row;
        float4 val = make_float4(0.f, 0.f, 0.f, 0.f);
        if (gn >= 0 && gn < N_) val = *(const float4*)&vb[(long long)gn * DH_ + c4];
        *(float4*)&vt[row * VSTR + c4] = val;
    }
    __syncthreads();
    const float* ob = oat + (long long)bh * N_ * DH_;
    float* outb = outc + ((long long)b * N_ + n0) * DIM_ + h * DH_;
#pragma unroll 4
    for (int i = 0; i < 32; i++) {
        int idx = tid + i * 256;
        int nl = idx >> 6, d = idx & 63;
        float r = 0.f;
#pragma unroll
        for (int kk = 0; kk < KC_; kk++) r = fmaf(vt[(nl + kk) * VSTR + d], wc[kk], r);
        outb[(long long)nl * DIM_ + d] = ob[(long long)(n0 + nl) * DH_ + d] + r;
    }
}

// ------------------------- host launcher -------------------------
extern "C" void kernel_launch(void* const* d_in, const int* in_sizes, int n_in,
                              void* d_out, int out_size) {
    const float* x      = (const float*)d_in[0];
    const float* ln_w   = (const float*)d_in[1];
    const float* ln_b   = (const float*)d_in[2];
    const float* w_qkv  = (const float*)d_in[3];
    const float* w_out  = (const float*)d_in[4];
    const float* b_out  = (const float*)d_in[5];
    const float* w_conv = (const float*)d_in[6];
    float* out = (float*)d_out;

    float *p_xn, *p_q, *p_k, *p_v, *p_ql, *p_kl, *p_a2;
    float *p_zA, *p_zB, *p_xz, *p_t1, *p_t2, *p_a3v, *p_zv, *p_oat, *p_outc;
    cudaGetSymbolAddress((void**)&p_xn,  g_xn);
    cudaGetSymbolAddress((void**)&p_q,   g_q);
    cudaGetSymbolAddress((void**)&p_k,   g_k);
    cudaGetSymbolAddress((void**)&p_v,   g_v);
    cudaGetSymbolAddress((void**)&p_ql,  g_ql);
    cudaGetSymbolAddress((void**)&p_kl,  g_kl);
    cudaGetSymbolAddress((void**)&p_a2,  g_a2);
    cudaGetSymbolAddress((void**)&p_zA,  g_zA);
    cudaGetSymbolAddress((void**)&p_zB,  g_zB);
    cudaGetSymbolAddress((void**)&p_xz,  g_xz);
    cudaGetSymbolAddress((void**)&p_t1,  g_t1);
    cudaGetSymbolAddress((void**)&p_t2,  g_t2);
    cudaGetSymbolAddress((void**)&p_a3v, g_a3v);
    cudaGetSymbolAddress((void**)&p_zv,  g_zv);
    cudaGetSymbolAddress((void**)&p_oat, g_oat);
    cudaGetSymbolAddress((void**)&p_outc,g_outc);

    static int flash_attr_set = 0;
    if (!flash_attr_set) {
        cudaFuncSetAttribute(flash_kernel, cudaFuncAttributeMaxDynamicSharedMemorySize, FL_SMEM);
        flash_attr_set = 1;
    }

    const long long sL  = (long long)M_ * DH_;      // 16384
    const long long sM2 = (long long)M_ * M_;       // 65536

    // 1. LayerNorm
    ln_kernel<<<B_ * N_, 128>>>(x, ln_w, ln_b, p_xn);

    // 2. QKV GEMM [16384,512] @ [512,1536] -> scatter into q/k/v [bh,n,dh]
    mma_gemm<128, 128, 2, 1, false><<<dim3(12, 128, 1), 256>>>(
        p_xn, w_qkv, nullptr, 512, 512, 1536, 0, 0, 0, 0, 1.f, 0.f,
        nullptr, nullptr, p_q, p_k, p_v);

    // 3. Landmarks (mean over 16 tokens)
    landmark_kernel<<<(BH_ * M_ * DH_) / 256, 256>>>(p_q, p_k, p_ql, p_kl);

    // 4. sim2 = ql @ kl^T [256,256] + softmax
    mma_gemm<128, 128, 2, 0, true><<<dim3(2, 2, BH_), 256>>>(
        p_ql, p_kl, p_a2, 64, 64, 64, 256, sL, sL, sM2, 1.f, 0.f,
        nullptr, nullptr, nullptr, nullptr, nullptr);
    softmax_kernel<<<BH_ * M_, 256>>>(p_a2);

    // 5. flash3: a3v = softmax(ql @ k^T) @ v   [bh,256,64]
    flash_kernel<<<dim3(M_ / 64, BH_), 128, FL_SMEM>>>(p_ql, p_k, p_v, p_a3v, N_);

    // 6. pinv init
    init_max_kernel<<<1, 32>>>();
    rowsum_max_kernel<<<BH_ * M_, 256>>>(p_a2);
    colsum_max_kernel<<<BH_ * M_, 256>>>(p_a2);
    zinit_kernel<<<(BH_ * M_ * M_) / 256, 256>>>(p_a2, p_zA);

    // 7. Newton-Schulz iterations (batched 256^3 GEMMs, 32 matrices)
    float* cur = p_zA;
    float* nxt = p_zB;
    for (int it = 0; it < ITERS_; it++) {
        mma_gemm<128, 128, 2, 0, false><<<dim3(2, 2, BH_), 256>>>(
            p_a2, cur, p_xz, 256, 256, 256, 256, sM2, sM2, sM2, 1.f, 0.f,
            nullptr, nullptr, nullptr, nullptr, nullptr);
        mma_gemm<128, 128, 2, 0, false><<<dim3(2, 2, BH_), 256>>>(
            p_xz, p_xz, p_t1, 256, 256, 256, 256, sM2, sM2, sM2, -1.f, 7.f,
            nullptr, nullptr, nullptr, nullptr, nullptr);
        mma_gemm<128, 128, 2, 0, false><<<dim3(2, 2, BH_), 256>>>(
            p_xz, p_t1, p_t2, 256, 256, 256, 256, sM2, sM2, sM2, -1.f, 15.f,
            nullptr, nullptr, nullptr, nullptr, nullptr);
        mma_gemm<128, 128, 2, 0, false><<<dim3(2, 2, BH_), 256>>>(
            cur, p_t2, nxt, 256, 256, 256, 256, sM2, sM2, sM2, -0.25f, 3.25f,
            nullptr, nullptr, nullptr, nullptr, nullptr);
        float* tmp = cur; cur = nxt; nxt = tmp;
    }

    // 8. zv = a2inv @ a3v  [256,64]
    mma_gemm<128, 64, 4, 0, false><<<dim3(1, 2, BH_), 256>>>(
        cur, p_a3v, p_zv, 256, 256, 64, 64, sM2, sL, sL, 1.f, 0.f,
        nullptr, nullptr, nullptr, nullptr, nullptr);

    // 9. flash1: oat = softmax(q @ kl^T) @ zv   [bh,4096,64]
    flash_kernel<<<dim3(N_ / 64, BH_), 128, FL_SMEM>>>(p_q, p_kl, p_zv, p_oat, M_);

    // 10. depthwise conv residual + head merge -> [b*n, 512]
    conv_merge_kernel<<<dim3(N_ / 128, BH_), 256>>>(p_v, p_oat, w_conv, p_outc);

    // 11. final: out = x + outc @ w_out + b_out
    mma_gemm<128, 128, 2, 2, false><<<dim3(4, 128, 1), 256>>>(
        p_outc, w_out, out, 512, 512, 512, 512, 0, 0, 0, 1.f, 0.f,
        x, b_out, nullptr, nullptr, nullptr);
}